// round 2
// baseline (speedup 1.0000x reference)
#include <cuda_runtime.h>
#include <cuda_bf16.h>

// Fixed shapes per reference: B=4096 users, P=200 slots, tau=1.0
#define NB 4096
#define PMAX 200
#define NTHREADS 256

// Scratch (no device allocation allowed -> __device__ globals)
__device__ float g_block_loss[NB];
__device__ unsigned int g_done_count = 0;

__device__ __forceinline__ float fast_rcp(float x) {
    float r;
    asm("rcp.approx.f32 %0, %1;" : "=f"(r) : "f"(x));
    return r;
}

// One block per user. 16x16 thread tiling over the p x p pair matrix:
// thread (ty,tx) handles rows i = ty+16m, cols j = tx+16n. All 256 lanes
// stay active regardless of p -> MUFU pipe sees ~100% lane occupancy.
// Per pair: LDS + FADD + MUFU.RCP + FFMA  (MUFU-bound at 16 lanes/cyc/SM).
__global__ __launch_bounds__(NTHREADS) void sauc_kernel(
    const float* __restrict__ scores_pos,
    const float* __restrict__ scores_neg,
    const int* __restrict__ pos_counts,
    float* __restrict__ out)
{
    const int b = blockIdx.x;
    const int tid = threadIdx.x;
    const int tx = tid & 15;
    const int ty = tid >> 4;
    const int p = pos_counts[b];

    __shared__ float s_epos[PMAX];
    __shared__ float s_eneg[PMAX];
    __shared__ float s_warp[NTHREADS / 32];
    __shared__ unsigned int s_is_last;

    // Precompute exponentials once per element (tau = 1):
    // sigmoid(pos_i - neg_j) = E_i / (E_i + N_j),  E=exp(pos), N=exp(neg)
    if (tid < p) {
        s_epos[tid] = __expf(scores_pos[b * PMAX + tid]);
        s_eneg[tid] = __expf(scores_neg[b * PMAX + tid]);
    }
    __syncthreads();

    float acc = 0.0f;
    for (int i = ty; i < p; i += 16) {
        const float e = s_epos[i];
        int j = tx;
        // 4-way unrolled column loop (stride 16 per class, 64 per iter)
        for (; j + 48 < p; j += 64) {
            float n0 = s_eneg[j];
            float n1 = s_eneg[j + 16];
            float n2 = s_eneg[j + 32];
            float n3 = s_eneg[j + 48];
            float r0 = fast_rcp(e + n0);
            float r1 = fast_rcp(e + n1);
            float r2 = fast_rcp(e + n2);
            float r3 = fast_rcp(e + n3);
            acc = fmaf(e, r0, acc);
            acc = fmaf(e, r1, acc);
            acc = fmaf(e, r2, acc);
            acc = fmaf(e, r3, acc);
        }
        for (; j < p; j += 16) {
            acc = fmaf(e, fast_rcp(e + s_eneg[j]), acc);
        }
    }

    // Block reduction
    #pragma unroll
    for (int off = 16; off > 0; off >>= 1)
        acc += __shfl_down_sync(0xffffffffu, acc, off);
    if ((tid & 31) == 0) s_warp[tid >> 5] = acc;
    __syncthreads();
    if (tid == 0) {
        float v = 0.0f;
        #pragma unroll
        for (int w = 0; w < NTHREADS / 32; w++) v += s_warp[w];
        float pf = (float)p;
        g_block_loss[b] = 1.0f - v / (pf * pf);
        __threadfence();
        s_is_last = (atomicAdd(&g_done_count, 1u) == (unsigned)(NB - 1));
    }
    __syncthreads();

    // Last block to finish performs the deterministic fixed-tree mean.
    if (s_is_last) {
        __threadfence();  // acquire: make all g_block_loss writes visible
        __shared__ float s_red[NTHREADS];
        float a = 0.0f;
        #pragma unroll
        for (int i = tid; i < NB; i += NTHREADS)
            a += g_block_loss[i];
        s_red[tid] = a;
        __syncthreads();
        #pragma unroll
        for (int stride = NTHREADS / 2; stride >= 32; stride >>= 1) {
            if (tid < stride) s_red[tid] += s_red[tid + stride];
            __syncthreads();
        }
        if (tid < 32) {
            float v = s_red[tid];
            #pragma unroll
            for (int off = 16; off > 0; off >>= 1)
                v += __shfl_down_sync(0xffffffffu, v, off);
            if (tid == 0) {
                out[0] = v * (1.0f / (float)NB);
                g_done_count = 0;  // reset for next graph replay
            }
        }
    }
}

extern "C" void kernel_launch(void* const* d_in, const int* in_sizes, int n_in,
                              void* d_out, int out_size)
{
    const float* scores_pos = (const float*)d_in[0];
    const float* scores_neg = (const float*)d_in[1];
    const int*   pos_counts = (const int*)d_in[2];
    float* out = (float*)d_out;

    sauc_kernel<<<NB, NTHREADS>>>(scores_pos, scores_neg, pos_counts, out);
}

// round 3
// speedup vs baseline: 1.4373x; 1.4373x over previous
#include <cuda_runtime.h>
#include <cuda_bf16.h>

// Fixed shapes per reference: B=4096 users, P=200 slots, tau=1.0
#define NB 4096
#define PMAX 200
#define PCOLS 224          // PMAX padded to multiple of 32 (7 chunks of 32)
#define NTHREADS 256
#define PADV 1.0e30f       // big-finite pad: e/(e+PADV) ~ 1e-28 ~ 0, no NaN/inf poison

// Scratch (no device allocation allowed -> __device__ globals)
__device__ float g_block_loss[NB];
__device__ unsigned int g_done_count = 0;

__device__ __forceinline__ float fast_rcp(float x) {
    float r;
    asm("rcp.approx.f32 %0, %1;" : "=f"(r) : "f"(x));
    return r;
}

// One block per user. Lanes tx=tid&15 own column pairs (32c+2tx, 32c+2tx+1)
// via float2 LDS; ty=tid>>4 strides rows by 16. Column trip count nc=ceil(p/32)
// is uniform across the block (pad columns with 1e30 -> contribution ~0), so
// there is NO divergence in the hot loop.
// Fused 2-pair sigmoid: e/(e+n0)+e/(e+n1) = e*(a0+a1)*rcp(a0*a1)
//   per 2 pairs: 3 FADD + 2 FMUL + 1 FFMA (6 fma-pipe) + 1 MUFU.RCP + 1 LDS.64
__global__ __launch_bounds__(NTHREADS) void sauc_kernel(
    const float* __restrict__ scores_pos,
    const float* __restrict__ scores_neg,
    const int* __restrict__ pos_counts,
    float* __restrict__ out)
{
    const int b = blockIdx.x;
    const int tid = threadIdx.x;
    const int tx = tid & 15;
    const int ty = tid >> 4;
    const int p = pos_counts[b];

    __shared__ float s_epos[PMAX];
    __shared__ float s_eneg[PCOLS];
    __shared__ float s_warp[NTHREADS / 32];
    __shared__ unsigned int s_is_last;

    // Precompute exponentials once per element (tau = 1):
    // sigmoid(pos_i - neg_j) = E_i / (E_i + N_j), E=exp(pos), N=exp(neg)
    if (tid < p) {
        s_epos[tid] = __expf(scores_pos[b * PMAX + tid]);
        s_eneg[tid] = __expf(scores_neg[b * PMAX + tid]);
    } else if (tid < PCOLS) {
        s_eneg[tid] = PADV;
    }
    __syncthreads();

    const float2* __restrict__ neg2 = (const float2*)s_eneg;
    const int nc = (p + 31) >> 5;   // uniform across block: 1..7 chunks of 32 cols

    float acc = 0.0f;
    for (int i = ty; i < p; i += 16) {
        const float e = s_epos[i];
        int c = 0;
        // 2 chunks per iter = 4 pairs per thread per iter
        for (; c + 2 <= nc; c += 2) {
            float2 nA = neg2[(c << 4) + tx];
            float2 nB = neg2[(c << 4) + 16 + tx];
            float a0 = e + nA.x;
            float a1 = e + nA.y;
            float b0 = e + nB.x;
            float b1 = e + nB.y;
            float sA = a0 + a1;
            float sB = b0 + b1;
            float dA = a0 * a1;
            float dB = b0 * b1;
            float rA = fast_rcp(dA);
            float rB = fast_rcp(dB);
            acc = fmaf(e * sA, rA, acc);
            acc = fmaf(e * sB, rB, acc);
        }
        if (c < nc) {
            float2 nA = neg2[(c << 4) + tx];
            float a0 = e + nA.x;
            float a1 = e + nA.y;
            float sA = a0 + a1;
            float dA = a0 * a1;
            acc = fmaf(e * sA, fast_rcp(dA), acc);
        }
    }

    // Block reduction
    #pragma unroll
    for (int off = 16; off > 0; off >>= 1)
        acc += __shfl_down_sync(0xffffffffu, acc, off);
    if ((tid & 31) == 0) s_warp[tid >> 5] = acc;
    __syncthreads();
    if (tid == 0) {
        float v = 0.0f;
        #pragma unroll
        for (int w = 0; w < NTHREADS / 32; w++) v += s_warp[w];
        float pf = (float)p;
        g_block_loss[b] = 1.0f - v / (pf * pf);
        __threadfence();
        s_is_last = (atomicAdd(&g_done_count, 1u) == (unsigned)(NB - 1));
    }
    __syncthreads();

    // Last block to finish performs the deterministic fixed-tree mean.
    if (s_is_last) {
        __threadfence();  // acquire: all g_block_loss writes visible
        __shared__ float s_red[NTHREADS];
        float a = 0.0f;
        #pragma unroll
        for (int i = tid; i < NB; i += NTHREADS)
            a += g_block_loss[i];
        s_red[tid] = a;
        __syncthreads();
        #pragma unroll
        for (int stride = NTHREADS / 2; stride >= 32; stride >>= 1) {
            if (tid < stride) s_red[tid] += s_red[tid + stride];
            __syncthreads();
        }
        if (tid < 32) {
            float v = s_red[tid];
            #pragma unroll
            for (int off = 16; off > 0; off >>= 1)
                v += __shfl_down_sync(0xffffffffu, v, off);
            if (tid == 0) {
                out[0] = v * (1.0f / (float)NB);
                g_done_count = 0;  // reset for next graph replay
            }
        }
    }
}

extern "C" void kernel_launch(void* const* d_in, const int* in_sizes, int n_in,
                              void* d_out, int out_size)
{
    const float* scores_pos = (const float*)d_in[0];
    const float* scores_neg = (const float*)d_in[1];
    const int*   pos_counts = (const int*)d_in[2];
    float* out = (float*)d_out;

    sauc_kernel<<<NB, NTHREADS>>>(scores_pos, scores_neg, pos_counts, out);
}

// round 6
// speedup vs baseline: 1.9300x; 1.3428x over previous
#include <cuda_runtime.h>
#include <cuda_bf16.h>

// Fixed shapes per reference: B=4096 users, P=200 slots, tau=1.0
#define NB 4096
#define PMAX 200
#define PCOLS 224          // PMAX padded to 7 chunks of 32
#define NTHREADS 256
#define PADV 1.0e30f       // pad: q=PADV*PADV overflows to +inf -> rcp(d)=0 -> term 0

// Scratch (no device allocation allowed -> __device__ globals)
__device__ float g_block_loss[NB];
__device__ unsigned int g_done_count = 0;

__device__ __forceinline__ float fast_rcp(float x) {
    float r;
    asm("rcp.approx.f32 %0, %1;" : "=f"(r) : "f"(x));
    return r;
}

// Fused 2-pair sigmoid with per-user precomputed column registers:
//   e/(e+n0) + e/(e+n1) = e*(2e+m) / (e^2 + e*m + q),  m=n0+n1, q=n0*n1
//   per 2 pairs: u=e+m (FADD), d=fma(e,u,q), t=fma(e,m,2e2), acc=fma(t,rcp(d),acc)
//   = 4 fma-pipe + 1 MUFU.RCP, no LDS, no integer ops in the chunk dimension.
template<int NC>
__device__ __forceinline__ float pair_sum(const float* __restrict__ s_epos,
                                          const float2* __restrict__ neg2,
                                          int p, int tx, int ty)
{
    float m[NC], q[NC];
    #pragma unroll
    for (int c = 0; c < NC; c++) {
        float2 n = neg2[c * 16 + tx];
        m[c] = n.x + n.y;
        q[c] = n.x * n.y;
    }
    float acc0 = 0.0f, acc1 = 0.0f;
    #pragma unroll 2
    for (int i = ty; i < p; i += 16) {
        const float e  = s_epos[i];
        const float w2 = e * (e + e);        // 2*e^2
        #pragma unroll
        for (int c = 0; c < NC; c++) {
            float u = e + m[c];
            float d = fmaf(e, u, q[c]);      // (e+n0)(e+n1)
            float t = fmaf(e, m[c], w2);     // e*(2e+m)
            float r = fast_rcp(d);
            if (c & 1) acc1 = fmaf(t, r, acc1);
            else       acc0 = fmaf(t, r, acc0);
        }
    }
    return acc0 + acc1;
}

__global__ __launch_bounds__(NTHREADS) void sauc_kernel(
    const float* __restrict__ scores_pos,
    const float* __restrict__ scores_neg,
    const int* __restrict__ pos_counts,
    float* __restrict__ out)
{
    const int b = blockIdx.x;
    const int tid = threadIdx.x;
    const int tx = tid & 15;
    const int ty = tid >> 4;
    const int p = pos_counts[b];

    __shared__ float s_epos[PMAX];
    __shared__ __align__(8) float s_eneg[PCOLS];   // 8B-aligned for float2 LDS.64
    __shared__ float s_warp[NTHREADS / 32];
    __shared__ unsigned int s_is_last;

    // Precompute exponentials once per element (tau=1):
    // sigmoid(pos_i - neg_j) = E_i/(E_i+N_j), E=exp(pos), N=exp(neg)
    if (tid < p) {
        s_epos[tid] = __expf(scores_pos[b * PMAX + tid]);
        s_eneg[tid] = __expf(scores_neg[b * PMAX + tid]);
    } else if (tid < PCOLS) {
        s_eneg[tid] = PADV;
    }
    __syncthreads();

    const float2* neg2 = (const float2*)s_eneg;
    const int nc = (p + 31) >> 5;   // uniform across block: 1..7

    float acc;
    switch (nc) {
        case 1:  acc = pair_sum<1>(s_epos, neg2, p, tx, ty); break;
        case 2:  acc = pair_sum<2>(s_epos, neg2, p, tx, ty); break;
        case 3:  acc = pair_sum<3>(s_epos, neg2, p, tx, ty); break;
        case 4:  acc = pair_sum<4>(s_epos, neg2, p, tx, ty); break;
        case 5:  acc = pair_sum<5>(s_epos, neg2, p, tx, ty); break;
        case 6:  acc = pair_sum<6>(s_epos, neg2, p, tx, ty); break;
        default: acc = pair_sum<7>(s_epos, neg2, p, tx, ty); break;
    }

    // Block reduction
    #pragma unroll
    for (int off = 16; off > 0; off >>= 1)
        acc += __shfl_down_sync(0xffffffffu, acc, off);
    if ((tid & 31) == 0) s_warp[tid >> 5] = acc;
    __syncthreads();
    if (tid == 0) {
        float v = 0.0f;
        #pragma unroll
        for (int w = 0; w < NTHREADS / 32; w++) v += s_warp[w];
        float pf = (float)p;
        g_block_loss[b] = 1.0f - v / (pf * pf);
        __threadfence();
        s_is_last = (atomicAdd(&g_done_count, 1u) == (unsigned)(NB - 1));
    }
    __syncthreads();

    // Last block to finish performs the deterministic fixed-tree mean.
    if (s_is_last) {
        __threadfence();  // all g_block_loss writes visible
        __shared__ float s_red[NTHREADS];
        float a = 0.0f;
        #pragma unroll
        for (int i = tid; i < NB; i += NTHREADS)
            a += g_block_loss[i];
        s_red[tid] = a;
        __syncthreads();
        #pragma unroll
        for (int stride = NTHREADS / 2; stride >= 32; stride >>= 1) {
            if (tid < stride) s_red[tid] += s_red[tid + stride];
            __syncthreads();
        }
        if (tid < 32) {
            float v = s_red[tid];
            #pragma unroll
            for (int off = 16; off > 0; off >>= 1)
                v += __shfl_down_sync(0xffffffffu, v, off);
            if (tid == 0) {
                out[0] = v * (1.0f / (float)NB);
                g_done_count = 0;  // reset for next graph replay
            }
        }
    }
}

extern "C" void kernel_launch(void* const* d_in, const int* in_sizes, int n_in,
                              void* d_out, int out_size)
{
    const float* scores_pos = (const float*)d_in[0];
    const float* scores_neg = (const float*)d_in[1];
    const int*   pos_counts = (const int*)d_in[2];
    float* out = (float*)d_out;

    sauc_kernel<<<NB, NTHREADS>>>(scores_pos, scores_neg, pos_counts, out);
}

// round 7
// speedup vs baseline: 1.9369x; 1.0036x over previous
#include <cuda_runtime.h>
#include <cuda_bf16.h>

// Fixed shapes per reference: B=4096 users, P=200 slots, tau=1.0
#define NB 4096
#define PMAX 200
#define PCOLS 224          // PMAX padded to 7 chunks of 32
#define NTHREADS 256
#define PADV 1.0e30f       // col pad: q -> inf => rcp(d)=0 => term 0

// Scratch (no device allocation allowed -> __device__ globals)
__device__ float g_block_loss[NB];
__device__ unsigned int g_done_count = 0;

__device__ __forceinline__ float fast_rcp(float x) {
    float r;
    asm("rcp.approx.f32 %0, %1;" : "=f"(r) : "f"(x));
    return r;
}

// Fused 2-col sigmoid with per-user register columns (m=n0+n1, q=n0*n1):
//   e/(e+n0)+e/(e+n1) = e*(2e+m) / fma(e, e+m, q)
// Two adjacent rows per thread per iteration (one LDS.64), zero-padded rows
// contribute exactly 0 (w2=0, t=0), so the row trip nr=ceil(p/32) is uniform.
template<int NC>
__device__ __forceinline__ float pair_sum(const float2* __restrict__ pos2,
                                          const float2* __restrict__ neg2,
                                          int nr, int tx, int ty)
{
    float m[NC], q[NC];
    #pragma unroll
    for (int c = 0; c < NC; c++) {
        float2 n = neg2[c * 16 + tx];
        m[c] = n.x + n.y;
        q[c] = n.x * n.y;
    }
    float acc0 = 0.0f, acc1 = 0.0f;
    for (int r = 0; r < nr; r++) {
        float2 e01 = pos2[r * 16 + ty];          // rows 32r+2ty, 32r+2ty+1
        const float e0 = e01.x, e1 = e01.y;
        const float w20 = e0 * (e0 + e0);        // 2*e0^2
        const float w21 = e1 * (e1 + e1);        // 2*e1^2
        #pragma unroll
        for (int c = 0; c < NC; c++) {
            float u0 = e0 + m[c];
            float u1 = e1 + m[c];
            float d0 = fmaf(e0, u0, q[c]);
            float d1 = fmaf(e1, u1, q[c]);
            float t0 = fmaf(e0, m[c], w20);
            float t1 = fmaf(e1, m[c], w21);
            float r0 = fast_rcp(d0);
            float r1 = fast_rcp(d1);
            acc0 = fmaf(t0, r0, acc0);
            acc1 = fmaf(t1, r1, acc1);
        }
    }
    return acc0 + acc1;
}

__global__ __launch_bounds__(NTHREADS) void sauc_kernel(
    const float* __restrict__ scores_pos,
    const float* __restrict__ scores_neg,
    const int* __restrict__ pos_counts,
    float* __restrict__ out)
{
    const int b = blockIdx.x;
    const int tid = threadIdx.x;
    const int tx = tid & 15;
    const int ty = tid >> 4;
    const int p = pos_counts[b];

    __shared__ __align__(8) float s_epos[PCOLS];   // rows, zero-padded
    __shared__ __align__(8) float s_eneg[PCOLS];   // cols, PADV-padded
    __shared__ float s_warp[NTHREADS / 32];
    __shared__ unsigned int s_is_last;

    // Precompute exponentials once per element (tau=1):
    // sigmoid(pos_i - neg_j) = E_i/(E_i+N_j), E=exp(pos), N=exp(neg)
    if (tid < p) {
        s_epos[tid] = __expf(scores_pos[b * PMAX + tid]);
        s_eneg[tid] = __expf(scores_neg[b * PMAX + tid]);
    } else if (tid < PCOLS) {
        s_epos[tid] = 0.0f;   // zero row -> contributes exactly 0
        s_eneg[tid] = PADV;   // huge col -> rcp(inf)=0 -> contributes 0
    }
    __syncthreads();

    const float2* pos2 = (const float2*)s_epos;
    const float2* neg2 = (const float2*)s_eneg;
    const int nc = (p + 31) >> 5;   // uniform across block: 1..7

    float acc;
    switch (nc) {
        case 1:  acc = pair_sum<1>(pos2, neg2, 1, tx, ty); break;
        case 2:  acc = pair_sum<2>(pos2, neg2, 2, tx, ty); break;
        case 3:  acc = pair_sum<3>(pos2, neg2, 3, tx, ty); break;
        case 4:  acc = pair_sum<4>(pos2, neg2, 4, tx, ty); break;
        case 5:  acc = pair_sum<5>(pos2, neg2, 5, tx, ty); break;
        case 6:  acc = pair_sum<6>(pos2, neg2, 6, tx, ty); break;
        default: acc = pair_sum<7>(pos2, neg2, 7, tx, ty); break;
    }

    // Block reduction
    #pragma unroll
    for (int off = 16; off > 0; off >>= 1)
        acc += __shfl_down_sync(0xffffffffu, acc, off);
    if ((tid & 31) == 0) s_warp[tid >> 5] = acc;
    __syncthreads();
    if (tid == 0) {
        float v = 0.0f;
        #pragma unroll
        for (int w = 0; w < NTHREADS / 32; w++) v += s_warp[w];
        float pf = (float)p;
        g_block_loss[b] = 1.0f - v / (pf * pf);
        __threadfence();
        s_is_last = (atomicAdd(&g_done_count, 1u) == (unsigned)(NB - 1));
    }
    __syncthreads();

    // Last block to finish performs the deterministic fixed-tree mean.
    if (s_is_last) {
        __threadfence();  // all g_block_loss writes visible
        __shared__ float s_red[NTHREADS];
        float a = 0.0f;
        #pragma unroll
        for (int i = tid; i < NB; i += NTHREADS)
            a += g_block_loss[i];
        s_red[tid] = a;
        __syncthreads();
        #pragma unroll
        for (int stride = NTHREADS / 2; stride >= 32; stride >>= 1) {
            if (tid < stride) s_red[tid] += s_red[tid + stride];
            __syncthreads();
        }
        if (tid < 32) {
            float v = s_red[tid];
            #pragma unroll
            for (int off = 16; off > 0; off >>= 1)
                v += __shfl_down_sync(0xffffffffu, v, off);
            if (tid == 0) {
                out[0] = v * (1.0f / (float)NB);
                g_done_count = 0;  // reset for next graph replay
            }
        }
    }
}

extern "C" void kernel_launch(void* const* d_in, const int* in_sizes, int n_in,
                              void* d_out, int out_size)
{
    const float* scores_pos = (const float*)d_in[0];
    const float* scores_neg = (const float*)d_in[1];
    const int*   pos_counts = (const int*)d_in[2];
    float* out = (float*)d_out;

    sauc_kernel<<<NB, NTHREADS>>>(scores_pos, scores_neg, pos_counts, out);
}